// round 1
// baseline (speedup 1.0000x reference)
#include <cuda_runtime.h>
#include <cuda_bf16.h>

// WeightedAverage: 3x3 local softmax over L-channel differences, weighted
// average of a/b channels. x_lab [N,3,H,W] fp32 -> out [N,2,H,W] fp32.
// alpha=1, patch=3 (fixed by setup_inputs).

#define H 512
#define W 512
#define TX 32        // threads x
#define TY 8         // threads y
#define PXT 4        // pixels per thread along x
#define TILE_W (TX * PXT)   // 128
#define TILE_H TY           // 8
#define SROW 132            // smem row stride in floats (>=130, mult of 4)
#define SCH  (10 * SROW)    // floats per channel tile (10 halo rows)

__global__ __launch_bounds__(TX * TY) void wavg_kernel(
    const float* __restrict__ x, float* __restrict__ out, int N)
{
    __shared__ __align__(16) float sm[3 * SCH];   // L, a, b halo tiles

    const int n  = blockIdx.z;
    const int x0 = blockIdx.x * TILE_W;
    const int y0 = blockIdx.y * TILE_H;
    const int tid = threadIdx.y * TX + threadIdx.x;

    // ---- cooperative halo load: 3 channels x 10 rows x 130 cols ----
    const long plane = (long)H * W;
    const float* base = x + (long)n * 3 * plane;
    const int NLOAD = 3 * 10 * 130;
    #pragma unroll 4
    for (int i = tid; i < NLOAD; i += TX * TY) {
        int c   = i / 1300;
        int rem = i - c * 1300;
        int r   = rem / 130;
        int k   = rem - r * 130;
        int gy = y0 + r - 1;
        int gx = x0 + k - 1;
        float v = 0.0f;
        if (gy >= 0 && gy < H && gx >= 0 && gx < W)
            v = base[(long)c * plane + (long)gy * W + gx];
        sm[c * SCH + r * SROW + k] = v;
    }
    __syncthreads();

    const int ty = threadIdx.y;
    const int tx = threadIdx.x;
    const float* smL = sm;
    const float* smA = sm + SCH;
    const float* smB = sm + 2 * SCH;
    const int colb = tx * PXT;          // aligned smem col base (16B)

    // center L values: row ty+1, smem cols colb+1 .. colb+4
    float lc[PXT];
    {
        const float* p = smL + (ty + 1) * SROW + colb;
        float4 c0 = *(const float4*)p;
        float4 c1 = *(const float4*)(p + 4);
        lc[0] = c0.y; lc[1] = c0.z; lc[2] = c0.w; lc[3] = c1.x;
    }

    float den[PXT] = {0.f, 0.f, 0.f, 0.f};
    float wa [PXT] = {0.f, 0.f, 0.f, 0.f};
    float wb [PXT] = {0.f, 0.f, 0.f, 0.f};

    #pragma unroll
    for (int rr = 0; rr < 3; rr++) {
        const int off = (ty + rr) * SROW + colb;
        float4 l0 = *(const float4*)(smL + off);
        float4 l1 = *(const float4*)(smL + off + 4);
        float4 a0 = *(const float4*)(smA + off);
        float4 a1 = *(const float4*)(smA + off + 4);
        float4 b0 = *(const float4*)(smB + off);
        float4 b1 = *(const float4*)(smB + off + 4);
        float lr[8] = {l0.x, l0.y, l0.z, l0.w, l1.x, l1.y, l1.z, l1.w};
        float ar[8] = {a0.x, a0.y, a0.z, a0.w, a1.x, a1.y, a1.z, a1.w};
        float br[8] = {b0.x, b0.y, b0.z, b0.w, b1.x, b1.y, b1.z, b1.w};

        #pragma unroll
        for (int p = 0; p < PXT; p++) {
            #pragma unroll
            for (int dx = 0; dx < 3; dx++) {
                float d = lr[p + dx] - lc[p];
                float w = __expf(-d * d);
                den[p] += w;
                wa[p]  = fmaf(w, ar[p + dx], wa[p]);
                wb[p]  = fmaf(w, br[p + dx], wb[p]);
            }
        }
    }

    // ---- write output: [N,2,H,W], vectorized float4 stores ----
    const int gy = y0 + ty;
    const int gx = x0 + colb;
    float4 oa, ob;
    float inv0 = __fdividef(1.0f, den[0]);
    float inv1 = __fdividef(1.0f, den[1]);
    float inv2 = __fdividef(1.0f, den[2]);
    float inv3 = __fdividef(1.0f, den[3]);
    oa.x = wa[0] * inv0; oa.y = wa[1] * inv1; oa.z = wa[2] * inv2; oa.w = wa[3] * inv3;
    ob.x = wb[0] * inv0; ob.y = wb[1] * inv1; ob.z = wb[2] * inv2; ob.w = wb[3] * inv3;

    float* outp = out + ((long)n * 2) * plane + (long)gy * W + gx;
    *(float4*)outp            = oa;
    *(float4*)(outp + plane)  = ob;
}

extern "C" void kernel_launch(void* const* d_in, const int* in_sizes, int n_in,
                              void* d_out, int out_size)
{
    const float* x = (const float*)d_in[0];
    float* out = (float*)d_out;
    int N = in_sizes[0] / (3 * H * W);   // 16

    dim3 block(TX, TY);
    dim3 grid(W / TILE_W, H / TILE_H, N);
    wavg_kernel<<<grid, block>>>(x, out, N);
}

// round 2
// speedup vs baseline: 1.2741x; 1.2741x over previous
#include <cuda_runtime.h>
#include <cuda_bf16.h>

// WeightedAverage: 3x3 local softmax over L-channel diffs, weighted average
// of a/b channels. x_lab [N,3,512,512] fp32 -> out [N,2,512,512] fp32.
// alpha=1, patch=3.
//
// R1 version: vectorized (float4) halo load with cheap indexing, 2 output
// rows per thread (window-row reuse), center-tap exp skipped (w==1).

#define H 512
#define W 512
#define TX 32
#define TY 8
#define TILE_W 128           // 32 threads * 4 px
#define TILE_H 16            // 8 thread-rows * 2 rows each
#define HROWS 18             // TILE_H + 2 halo rows
#define SROW 132             // smem floats per row (130 used, padded)
#define SCH (HROWS * SROW)
#define NCHUNK 34            // float4 chunks per halo row (cols x0-4 .. x0+131)
#define NVEC (3 * HROWS * NCHUNK)   // 1836

__global__ __launch_bounds__(256, 4) void wavg_kernel(
    const float* __restrict__ x, float* __restrict__ out)
{
    __shared__ __align__(16) float sm[3 * SCH];

    const int n  = blockIdx.z;
    const int x0 = blockIdx.x * TILE_W;
    const int y0 = blockIdx.y * TILE_H;
    const int tid = threadIdx.y * TX + threadIdx.x;
    const long plane = (long)H * W;
    const float* base = x + (long)n * 3 * plane;

    // ---- cooperative vectorized halo load ----
    // smem col s corresponds to gx = x0 - 1 + s, s in [0,130)
    // global float4 chunk k covers gx = x0-4+4k .. x0-1+4k -> s = 4k-3 .. 4k
    #pragma unroll
    for (int i = tid; i < NVEC; i += 256) {
        int rowid = i / NCHUNK;            // 0..53
        int k     = i - rowid * NCHUNK;    // 0..33
        int c     = rowid / HROWS;         // channel 0..2
        int r     = rowid - c * HROWS;     // halo row 0..17
        int gy  = y0 + r - 1;
        int gx0 = x0 + 4 * k - 4;
        float4 v = make_float4(0.f, 0.f, 0.f, 0.f);
        if ((unsigned)gy < (unsigned)H && (unsigned)gx0 <= (unsigned)(W - 4))
            v = *(const float4*)(base + (long)c * plane + (long)gy * W + gx0);
        float* srow = sm + c * SCH + r * SROW;
        int s = 4 * k - 3;
        if (k >= 1) {
            srow[s] = v.x;
            if (k <= 32) { srow[s + 1] = v.y; srow[s + 2] = v.z; }
        }
        if (k <= 32) srow[s + 3] = v.w;
    }
    __syncthreads();

    const int tx = threadIdx.x, ty = threadIdx.y;
    const int r0 = 2 * ty;          // window rows r0..r0+3; outputs tile rows r0, r0+1
    const int sc = 4 * tx;          // aligned smem col base; px p center at s = sc+p+1
    const float* smL = sm;
    const float* smA = sm + SCH;
    const float* smB = sm + 2 * SCH;

    // preload L rows r0+1 (center of output 0) and r0+2 (center of output 1)
    float l1r[8], l2r[8];
    {
        const float* p1 = smL + (r0 + 1) * SROW + sc;
        float4 u0 = *(const float4*)p1;
        float4 u1 = *(const float4*)(p1 + 4);
        l1r[0]=u0.x; l1r[1]=u0.y; l1r[2]=u0.z; l1r[3]=u0.w;
        l1r[4]=u1.x; l1r[5]=u1.y; l1r[6]=u1.z; l1r[7]=u1.w;
        const float* p2 = smL + (r0 + 2) * SROW + sc;
        float4 w0 = *(const float4*)p2;
        float4 w1 = *(const float4*)(p2 + 4);
        l2r[0]=w0.x; l2r[1]=w0.y; l2r[2]=w0.z; l2r[3]=w0.w;
        l2r[4]=w1.x; l2r[5]=w1.y; l2r[6]=w1.z; l2r[7]=w1.w;
    }
    float lc[2][4];
    lc[0][0]=l1r[1]; lc[0][1]=l1r[2]; lc[0][2]=l1r[3]; lc[0][3]=l1r[4];
    lc[1][0]=l2r[1]; lc[1][1]=l2r[2]; lc[1][2]=l2r[3]; lc[1][3]=l2r[4];

    float den[2][4], wa[2][4], wb[2][4];
    #pragma unroll
    for (int q = 0; q < 2; q++)
        #pragma unroll
        for (int p = 0; p < 4; p++) { den[q][p]=0.f; wa[q][p]=0.f; wb[q][p]=0.f; }

    #pragma unroll
    for (int wr = 0; wr < 4; wr++) {
        const int off = (r0 + wr) * SROW + sc;
        float l[8], a[8], b[8];
        if (wr == 1) {
            #pragma unroll
            for (int t = 0; t < 8; t++) l[t] = l1r[t];
        } else if (wr == 2) {
            #pragma unroll
            for (int t = 0; t < 8; t++) l[t] = l2r[t];
        } else {
            float4 u0 = *(const float4*)(smL + off);
            float4 u1 = *(const float4*)(smL + off + 4);
            l[0]=u0.x; l[1]=u0.y; l[2]=u0.z; l[3]=u0.w;
            l[4]=u1.x; l[5]=u1.y; l[6]=u1.z; l[7]=u1.w;
        }
        {
            float4 u0 = *(const float4*)(smA + off);
            float4 u1 = *(const float4*)(smA + off + 4);
            a[0]=u0.x; a[1]=u0.y; a[2]=u0.z; a[3]=u0.w;
            a[4]=u1.x; a[5]=u1.y; a[6]=u1.z; a[7]=u1.w;
            float4 v0 = *(const float4*)(smB + off);
            float4 v1 = *(const float4*)(smB + off + 4);
            b[0]=v0.x; b[1]=v0.y; b[2]=v0.z; b[3]=v0.w;
            b[4]=v1.x; b[5]=v1.y; b[6]=v1.z; b[7]=v1.w;
        }
        #pragma unroll
        for (int q = 0; q < 2; q++) {
            if (wr < q || wr > q + 2) continue;   // row outside this output's window
            const bool cen = (wr == q + 1);
            #pragma unroll
            for (int p = 0; p < 4; p++) {
                #pragma unroll
                for (int dx = 0; dx < 3; dx++) {
                    if (cen && dx == 1) {
                        // center tap: diff == 0 -> weight exactly 1
                        den[q][p] += 1.0f;
                        wa[q][p]  += a[p + 1];
                        wb[q][p]  += b[p + 1];
                    } else {
                        float d = l[p + dx] - lc[q][p];
                        float w = __expf(-d * d);
                        den[q][p] += w;
                        wa[q][p] = fmaf(w, a[p + dx], wa[q][p]);
                        wb[q][p] = fmaf(w, b[p + dx], wb[q][p]);
                    }
                }
            }
        }
    }

    // ---- output: [N,2,H,W], float4 stores for both rows, both channels ----
    const int gx = x0 + sc;
    float* outa = out + (long)n * 2 * plane + (long)(y0 + r0) * W + gx;
    #pragma unroll
    for (int q = 0; q < 2; q++) {
        float i0 = __fdividef(1.0f, den[q][0]);
        float i1 = __fdividef(1.0f, den[q][1]);
        float i2 = __fdividef(1.0f, den[q][2]);
        float i3 = __fdividef(1.0f, den[q][3]);
        float4 oa = make_float4(wa[q][0]*i0, wa[q][1]*i1, wa[q][2]*i2, wa[q][3]*i3);
        float4 ob = make_float4(wb[q][0]*i0, wb[q][1]*i1, wb[q][2]*i2, wb[q][3]*i3);
        *(float4*)(outa + (long)q * W)         = oa;
        *(float4*)(outa + (long)q * W + plane) = ob;
    }
}

extern "C" void kernel_launch(void* const* d_in, const int* in_sizes, int n_in,
                              void* d_out, int out_size)
{
    const float* x = (const float*)d_in[0];
    float* out = (float*)d_out;
    int N = in_sizes[0] / (3 * H * W);   // 16

    dim3 block(TX, TY);
    dim3 grid(W / TILE_W, H / TILE_H, N);
    wavg_kernel<<<grid, block>>>(x, out);
}

// round 5
// speedup vs baseline: 1.3579x; 1.0658x over previous
#include <cuda_runtime.h>
#include <cuda_bf16.h>

// WeightedAverage: 3x3 local softmax over L-channel diffs, weighted average
// of a/b channels. x_lab [N,3,512,512] fp32 -> out [N,2,512,512] fp32.
// alpha=1, patch=3.
//
// R2 version: PY=1 + center-row-first (low register pressure, occupancy 5
// blocks/SM), vectorized float4 halo load, center-tap exp skipped.

#define H 512
#define W 512
#define TX 32
#define TY 8
#define TILE_W 128           // 32 threads * 4 px
#define TILE_H 8             // 8 thread-rows * 1 row each
#define HROWS 10             // TILE_H + 2 halo rows
#define SROW 132             // smem floats per row (130 used, padded)
#define SCH (HROWS * SROW)
#define NCHUNK 34            // float4 chunks per halo row
#define NVEC (3 * HROWS * NCHUNK)   // 1020

// load 8 consecutive floats (16B-aligned) from smem into a float[8]
#define LD8(dst, ptr) do {                                   \
    float4 _u0 = *(const float4*)(ptr);                      \
    float4 _u1 = *(const float4*)((ptr) + 4);                \
    dst[0]=_u0.x; dst[1]=_u0.y; dst[2]=_u0.z; dst[3]=_u0.w;  \
    dst[4]=_u1.x; dst[5]=_u1.y; dst[6]=_u1.z; dst[7]=_u1.w;  \
} while (0)

__global__ __launch_bounds__(256, 5) void wavg_kernel(
    const float* __restrict__ x, float* __restrict__ out)
{
    __shared__ __align__(16) float sm[3 * SCH];

    const int n  = blockIdx.z;
    const int x0 = blockIdx.x * TILE_W;
    const int y0 = blockIdx.y * TILE_H;
    const int tid = threadIdx.y * TX + threadIdx.x;
    const long plane = (long)H * W;
    const float* base = x + (long)n * 3 * plane;

    // ---- cooperative vectorized halo load ----
    // smem col s <-> gx = x0 - 1 + s, s in [0,130)
    // chunk k covers gx = x0-4+4k .. x0-1+4k -> s = 4k-3 .. 4k
    #pragma unroll
    for (int i = tid; i < NVEC; i += 256) {
        int rowid = i / NCHUNK;            // 0..29
        int k     = i - rowid * NCHUNK;    // 0..33
        int c     = rowid / HROWS;         // channel 0..2
        int r     = rowid - c * HROWS;     // halo row 0..9
        int gy  = y0 + r - 1;
        int gx0 = x0 + 4 * k - 4;
        float4 v = make_float4(0.f, 0.f, 0.f, 0.f);
        if ((unsigned)gy < (unsigned)H && (unsigned)gx0 <= (unsigned)(W - 4))
            v = *(const float4*)(base + (long)c * plane + (long)gy * W + gx0);
        float* srow = sm + c * SCH + r * SROW;
        int s = 4 * k - 3;
        if (k >= 1) {
            srow[s] = v.x;
            if (k <= 32) { srow[s + 1] = v.y; srow[s + 2] = v.z; }
        }
        if (k <= 32) srow[s + 3] = v.w;
    }
    __syncthreads();

    const int tx = threadIdx.x, ty = threadIdx.y;
    const int sc = 4 * tx;               // aligned smem col; px p center at sc+p+1
    const float* smL = sm;
    const float* smA = sm + SCH;
    const float* smB = sm + 2 * SCH;

    float den[4], wa[4], wb[4], lc[4];

    // ---- center window row first: yields lc + free center tap (w == 1) ----
    {
        const int off = (ty + 1) * SROW + sc;
        float l[8], a[8], b[8];
        LD8(l, smL + off);
        LD8(a, smA + off);
        LD8(b, smB + off);
        #pragma unroll
        for (int p = 0; p < 4; p++) {
            lc[p]  = l[p + 1];
            den[p] = 1.0f;         // center tap: diff==0 -> weight exactly 1
            wa[p]  = a[p + 1];
            wb[p]  = b[p + 1];
        }
        #pragma unroll
        for (int p = 0; p < 4; p++) {
            #pragma unroll
            for (int dx = 0; dx < 3; dx += 2) {     // skip dx==1 (center)
                float d = l[p + dx] - lc[p];
                float w = __expf(-d * d);
                den[p] += w;
                wa[p] = fmaf(w, a[p + dx], wa[p]);
                wb[p] = fmaf(w, b[p + dx], wb[p]);
            }
        }
    }

    // ---- rows above (ty) and below (ty+2): full 3 taps ----
    #pragma unroll
    for (int rr = 0; rr < 2; rr++) {
        const int off = (ty + 2 * rr) * SROW + sc;
        float l[8], a[8], b[8];
        LD8(l, smL + off);
        LD8(a, smA + off);
        LD8(b, smB + off);
        #pragma unroll
        for (int p = 0; p < 4; p++) {
            #pragma unroll
            for (int dx = 0; dx < 3; dx++) {
                float d = l[p + dx] - lc[p];
                float w = __expf(-d * d);
                den[p] += w;
                wa[p] = fmaf(w, a[p + dx], wa[p]);
                wb[p] = fmaf(w, b[p + dx], wb[p]);
            }
        }
    }

    // ---- output: [N,2,H,W], float4 stores ----
    float i0 = __fdividef(1.0f, den[0]);
    float i1 = __fdividef(1.0f, den[1]);
    float i2 = __fdividef(1.0f, den[2]);
    float i3 = __fdividef(1.0f, den[3]);
    float4 oa = make_float4(wa[0]*i0, wa[1]*i1, wa[2]*i2, wa[3]*i3);
    float4 ob = make_float4(wb[0]*i0, wb[1]*i1, wb[2]*i2, wb[3]*i3);

    float* outp = out + (long)n * 2 * plane + (long)(y0 + ty) * W + (x0 + sc);
    *(float4*)outp           = oa;
    *(float4*)(outp + plane) = ob;
}

extern "C" void kernel_launch(void* const* d_in, const int* in_sizes, int n_in,
                              void* d_out, int out_size)
{
    const float* x = (const float*)d_in[0];
    float* out = (float*)d_out;
    int N = in_sizes[0] / (3 * H * W);   // 16

    dim3 block(TX, TY);
    dim3 grid(W / TILE_W, H / TILE_H, N);
    wavg_kernel<<<grid, block>>>(x, out);
}

// round 7
// speedup vs baseline: 1.4246x; 1.0491x over previous
#include <cuda_runtime.h>
#include <cuda_bf16.h>

// WeightedAverage: 3x3 local softmax over L-channel diffs, weighted average
// of a/b channels. x_lab [N,3,512,512] fp32 -> out [N,2,512,512] fp32.
// alpha=1, patch=3.
//
// R5 version: packed f32x2 math (FFMA2/FADD2/FMUL2 via PTX — 2 px per issue
// slot), pixel pairs (0,1) and (2,3), LDS.128+LDS.64 row loads (cols 0..5),
// center-row-first for lc + free center tap, vectorized halo load.

#define H 512
#define W 512
#define TX 32
#define TY 8
#define TILE_W 128           // 32 threads * 4 px
#define TILE_H 8
#define HROWS 10
#define SROW 132
#define SCH (HROWS * SROW)
#define NCHUNK 34
#define NVEC (3 * HROWS * NCHUNK)   // 1020

typedef unsigned long long u64;

__device__ __forceinline__ u64 PK(float lo, float hi) {
    u64 r; asm("mov.b64 %0, {%1, %2};" : "=l"(r) : "f"(lo), "f"(hi)); return r;
}
__device__ __forceinline__ void UPK(float& lo, float& hi, u64 v) {
    asm("mov.b64 {%0, %1}, %2;" : "=f"(lo), "=f"(hi) : "l"(v));
}
__device__ __forceinline__ u64 ADD2(u64 a, u64 b) {
    u64 r; asm("add.rn.f32x2 %0, %1, %2;" : "=l"(r) : "l"(a), "l"(b)); return r;
}
__device__ __forceinline__ u64 MUL2(u64 a, u64 b) {
    u64 r; asm("mul.rn.f32x2 %0, %1, %2;" : "=l"(r) : "l"(a), "l"(b)); return r;
}
__device__ __forceinline__ u64 FMA2(u64 a, u64 b, u64 c) {
    u64 r; asm("fma.rn.f32x2 %0, %1, %2, %3;" : "=l"(r) : "l"(a), "l"(b), "l"(c)); return r;
}

// row pairs: q0=(v0,v1) m1=(v1,v2) q1=(v2,v3) m2=(v3,v4) q2=(v4,v5)
struct Row { u64 q0, m1, q1, m2, q2; };

__device__ __forceinline__ Row load_row(const float* p) {
    float4 v = *(const float4*)p;          // cols 0..3
    float2 w = *(const float2*)(p + 4);    // cols 4..5
    Row r;
    r.q0 = PK(v.x, v.y);
    r.m1 = PK(v.y, v.z);
    r.q1 = PK(v.z, v.w);
    r.m2 = PK(v.w, w.x);
    r.q2 = PK(w.x, w.y);
    return r;
}

// w = exp(-(l - lc)^2) for a pixel pair; lcn = -lc pair, nl2e = (-log2e,-log2e)
__device__ __forceinline__ u64 wcalc(u64 lp, u64 lcn, u64 nl2e) {
    u64 d = ADD2(lp, lcn);
    u64 t = MUL2(d, d);
    u64 m = MUL2(t, nl2e);
    float m0, m1, w0, w1;
    UPK(m0, m1, m);
    asm("ex2.approx.f32 %0, %1;" : "=f"(w0) : "f"(m0));
    asm("ex2.approx.f32 %0, %1;" : "=f"(w1) : "f"(m1));
    return PK(w0, w1);
}

__global__ __launch_bounds__(256, 5) void wavg_kernel(
    const float* __restrict__ x, float* __restrict__ out)
{
    __shared__ __align__(16) float sm[3 * SCH];

    const int n  = blockIdx.z;
    const int x0 = blockIdx.x * TILE_W;
    const int y0 = blockIdx.y * TILE_H;
    const int tid = threadIdx.y * TX + threadIdx.x;
    const long plane = (long)H * W;
    const float* base = x + (long)n * 3 * plane;

    // ---- cooperative vectorized halo load ----
    #pragma unroll
    for (int i = tid; i < NVEC; i += 256) {
        int rowid = i / NCHUNK;
        int k     = i - rowid * NCHUNK;
        int c     = rowid / HROWS;
        int r     = rowid - c * HROWS;
        int gy  = y0 + r - 1;
        int gx0 = x0 + 4 * k - 4;
        float4 v = make_float4(0.f, 0.f, 0.f, 0.f);
        if ((unsigned)gy < (unsigned)H && (unsigned)gx0 <= (unsigned)(W - 4))
            v = *(const float4*)(base + (long)c * plane + (long)gy * W + gx0);
        float* srow = sm + c * SCH + r * SROW;
        int s = 4 * k - 3;
        if (k >= 1) {
            srow[s] = v.x;
            if (k <= 32) { srow[s + 1] = v.y; srow[s + 2] = v.z; }
        }
        if (k <= 32) srow[s + 3] = v.w;
    }
    __syncthreads();

    const int tx = threadIdx.x, ty = threadIdx.y;
    const int sc = 4 * tx;
    const float* smL = sm;
    const float* smA = sm + SCH;
    const float* smB = sm + 2 * SCH;

    const u64 nl2e = PK(-1.4426950408889634f, -1.4426950408889634f);

    u64 den0, den1, wa0, wa1, wb0, wb1, lcn0, lcn1;

    // ---- center window row first ----
    {
        const int off = (ty + 1) * SROW + sc;
        Row l = load_row(smL + off);
        // lc pairs = l.m1 (px 0,1), l.m2 (px 2,3); negate for ADD2-based diff
        {
            float a0, a1; UPK(a0, a1, l.m1); lcn0 = PK(-a0, -a1);
            float b0, b1; UPK(b0, b1, l.m2); lcn1 = PK(-b0, -b1);
        }
        // non-center taps of center row (dx = 0, 2)
        u64 w00 = wcalc(l.q0, lcn0, nl2e);
        u64 w02 = wcalc(l.q1, lcn0, nl2e);
        u64 w10 = wcalc(l.q1, lcn1, nl2e);
        u64 w12 = wcalc(l.q2, lcn1, nl2e);
        const u64 one2 = PK(1.0f, 1.0f);       // center tap weight
        den0 = ADD2(one2, ADD2(w00, w02));
        den1 = ADD2(one2, ADD2(w10, w12));

        Row a = load_row(smA + off);
        wa0 = a.m1;                            // center tap: w==1
        wa0 = FMA2(w00, a.q0, wa0);
        wa0 = FMA2(w02, a.q1, wa0);
        wa1 = a.m2;
        wa1 = FMA2(w10, a.q1, wa1);
        wa1 = FMA2(w12, a.q2, wa1);

        Row b = load_row(smB + off);
        wb0 = b.m1;
        wb0 = FMA2(w00, b.q0, wb0);
        wb0 = FMA2(w02, b.q1, wb0);
        wb1 = b.m2;
        wb1 = FMA2(w10, b.q1, wb1);
        wb1 = FMA2(w12, b.q2, wb1);
    }

    // ---- rows above (ty) and below (ty+2): full 3 taps ----
    #pragma unroll
    for (int rr = 0; rr < 2; rr++) {
        const int off = (ty + 2 * rr) * SROW + sc;
        Row l = load_row(smL + off);
        u64 w00 = wcalc(l.q0, lcn0, nl2e);
        u64 w01 = wcalc(l.m1, lcn0, nl2e);
        u64 w02 = wcalc(l.q1, lcn0, nl2e);
        u64 w10 = wcalc(l.q1, lcn1, nl2e);
        u64 w11 = wcalc(l.m2, lcn1, nl2e);
        u64 w12 = wcalc(l.q2, lcn1, nl2e);
        den0 = ADD2(den0, ADD2(w00, ADD2(w01, w02)));
        den1 = ADD2(den1, ADD2(w10, ADD2(w11, w12)));

        Row a = load_row(smA + off);
        wa0 = FMA2(w00, a.q0, wa0);
        wa0 = FMA2(w01, a.m1, wa0);
        wa0 = FMA2(w02, a.q1, wa0);
        wa1 = FMA2(w10, a.q1, wa1);
        wa1 = FMA2(w11, a.m2, wa1);
        wa1 = FMA2(w12, a.q2, wa1);

        Row b = load_row(smB + off);
        wb0 = FMA2(w00, b.q0, wb0);
        wb0 = FMA2(w01, b.m1, wb0);
        wb0 = FMA2(w02, b.q1, wb0);
        wb1 = FMA2(w10, b.q1, wb1);
        wb1 = FMA2(w11, b.m2, wb1);
        wb1 = FMA2(w12, b.q2, wb1);
    }

    // ---- epilogue: reciprocal + packed scale, float4 stores ----
    float d0, d1, d2, d3;
    UPK(d0, d1, den0);
    UPK(d2, d3, den1);
    float i0, i1, i2, i3;
    asm("rcp.approx.f32 %0, %1;" : "=f"(i0) : "f"(d0));
    asm("rcp.approx.f32 %0, %1;" : "=f"(i1) : "f"(d1));
    asm("rcp.approx.f32 %0, %1;" : "=f"(i2) : "f"(d2));
    asm("rcp.approx.f32 %0, %1;" : "=f"(i3) : "f"(d3));
    u64 iv0 = PK(i0, i1), iv1 = PK(i2, i3);

    u64 oa0 = MUL2(wa0, iv0), oa1 = MUL2(wa1, iv1);
    u64 ob0 = MUL2(wb0, iv0), ob1 = MUL2(wb1, iv1);

    float4 oa, ob;
    UPK(oa.x, oa.y, oa0); UPK(oa.z, oa.w, oa1);
    UPK(ob.x, ob.y, ob0); UPK(ob.z, ob.w, ob1);

    float* outp = out + (long)n * 2 * plane + (long)(y0 + ty) * W + (x0 + sc);
    *(float4*)outp           = oa;
    *(float4*)(outp + plane) = ob;
}

extern "C" void kernel_launch(void* const* d_in, const int* in_sizes, int n_in,
                              void* d_out, int out_size)
{
    const float* x = (const float*)d_in[0];
    float* out = (float*)d_out;
    int N = in_sizes[0] / (3 * H * W);   // 16

    dim3 block(TX, TY);
    dim3 grid(W / TILE_W, H / TILE_H, N);
    wavg_kernel<<<grid, block>>>(x, out);
}